// round 5
// baseline (speedup 1.0000x reference)
#include <cuda_runtime.h>
#include <math.h>

#define NN 100000
#define EE 1600000
#define HC 64          // H*C = 2*32
#define OUTC 40
#define NEGS 0.2f
#define NB_SCAN ((NN + 1023) / 1024)

// ---------------- scratch buffers (device globals) -------------------------
__device__ float g_xl [(size_t)NN * HC];   // transformed features (per layer)
__device__ float g_h  [(size_t)NN * HC];   // layer output (relu'd)
__device__ int   g_deg[NN];                // degree histogram
__device__ int   g_cur[NN];                // scatter cursor
__device__ int   g_off[NN + 1];            // CSR offsets (by dst)
__device__ int   g_adj[EE];                // CSR adjacency: src ids sorted by dst
__device__ int   g_bsum[NB_SCAN];          // scan block sums
__device__ float g_Wp [OUTC * HC];         // fused Wp2@Wp1  [40,64]
__device__ float g_bp [OUTC];              // fused bias

// --------------------------------------------------------------- tiled GEMM
// Y[n,64] = X[n,IC] @ W[64,IC]^T + b. Optionally zeroes degz[0..ndeg) too
// (piggyback: grid*block >= 4*n >= ndeg).
template<int IC>
__global__ __launch_bounds__(256) void gemm64(const float* __restrict__ X,
                                              const float* __restrict__ W,
                                              const float* __restrict__ b,
                                              float* __restrict__ Y, int n,
                                              int* __restrict__ degz, int ndeg) {
    if (degz) {
        int gid = blockIdx.x * 256 + threadIdx.x;
        if (gid < ndeg) degz[gid] = 0;
    }
    __shared__ float sX[64][33];
    __shared__ float sW[64][33];
    const int tx = threadIdx.x & 15;
    const int ty = threadIdx.x >> 4;
    const int rowBase = blockIdx.x * 64;

    float acc[4][4];
#pragma unroll
    for (int i = 0; i < 4; i++)
#pragma unroll
        for (int j = 0; j < 4; j++) acc[i][j] = 0.f;

    for (int k0 = 0; k0 < IC; k0 += 32) {
#pragma unroll
        for (int l = 0; l < 8; l++) {
            int idx = threadIdx.x + l * 256;
            int r = idx >> 5, kk = idx & 31;
            int row = rowBase + r;
            sX[r][kk] = (row < n) ? X[(size_t)row * IC + k0 + kk] : 0.f;
            sW[r][kk] = W[(size_t)r * IC + k0 + kk];
        }
        __syncthreads();
#pragma unroll
        for (int kk = 0; kk < 32; kk++) {
            float xv[4], wv[4];
#pragma unroll
            for (int i = 0; i < 4; i++) xv[i] = sX[ty * 4 + i][kk];
#pragma unroll
            for (int j = 0; j < 4; j++) wv[j] = sW[tx * 4 + j][kk];
#pragma unroll
            for (int i = 0; i < 4; i++)
#pragma unroll
                for (int j = 0; j < 4; j++) acc[i][j] += xv[i] * wv[j];
        }
        __syncthreads();
    }
#pragma unroll
    for (int i = 0; i < 4; i++) {
        int row = rowBase + ty * 4 + i;
        if (row < n) {
#pragma unroll
            for (int j = 0; j < 4; j++) {
                int col = tx * 4 + j;
                Y[(size_t)row * HC + col] = acc[i][j] + b[col];
            }
        }
    }
}

// ----------------------------------------------------------- CSR build chain
__global__ void hist_kernel(const int* __restrict__ dst, int* __restrict__ deg, int ne) {
    int e = blockIdx.x * blockDim.x + threadIdx.x;
    if (e < ne) atomicAdd(&deg[dst[e]], 1);
}

__global__ __launch_bounds__(1024) void scan1_kernel(const int* __restrict__ deg,
                                                     int* __restrict__ off,
                                                     int* __restrict__ bsum, int n) {
    __shared__ int sm[1024];
    int t = threadIdx.x;
    int i = blockIdx.x * 1024 + t;
    int v = (i < n) ? deg[i] : 0;
    sm[t] = v;
    __syncthreads();
#pragma unroll
    for (int d = 1; d < 1024; d <<= 1) {
        int add = (t >= d) ? sm[t - d] : 0;
        __syncthreads();
        sm[t] += add;
        __syncthreads();
    }
    if (i < n) off[i + 1] = sm[t];
    if (t == 1023) bsum[blockIdx.x] = sm[t];
}

// add cross-block prefix + zero cursors (merged old scan2 + scan3)
__global__ __launch_bounds__(256) void scan23_kernel(int* __restrict__ off,
                                                     const int* __restrict__ bsum,
                                                     int* __restrict__ cur, int n, int nb) {
    __shared__ int spref[2];
    int b0 = (blockIdx.x * 256) >> 10;
    if (threadIdx.x < 2) {
        int chunk = b0 + threadIdx.x;
        int p = 0;
        for (int k = 0; k < chunk && k < nb; k++) p += bsum[k];
        spref[threadIdx.x] = p;
    }
    __syncthreads();
    int i = blockIdx.x * 256 + threadIdx.x;
    if (i < n) {
        off[i + 1] += spref[(i >> 10) - b0];
        cur[i] = 0;
    }
    if (i == 0) off[0] = 0;
}

__global__ void scatter_kernel(const int* __restrict__ src, const int* __restrict__ dst,
                               const int* __restrict__ off, int* __restrict__ cur,
                               int* __restrict__ adj, int ne) {
    int e = blockIdx.x * blockDim.x + threadIdx.x;
    if (e >= ne) return;
    int d = dst[e];
    int pos = off[d] + atomicAdd(&cur[d], 1);
    adj[pos] = src[e];
}

// ----------------------------------------- node-centric fused GAT edge pass
// Two dst nodes per warp; 16 lanes/node, each lane owns 4 channels (float4).
__global__ __launch_bounds__(256) void gat_node_kernel(
    const int* __restrict__ adj, const int* __restrict__ off,
    const float* __restrict__ xl,
    const float* __restrict__ attl, const float* __restrict__ attr,
    float* __restrict__ h, int n) {
    int warp = (blockIdx.x * 256 + threadIdx.x) >> 5;
    int lane = threadIdx.x & 31;
    int half = lane >> 4;
    int l16  = lane & 15;
    int node = warp * 2 + half;
    int c = l16 * 4;
    bool valid = node < n;

    int beg = valid ? __ldg(&off[node])     : 0;
    int end = valid ? __ldg(&off[node + 1]) : 0;
    int deg = end - beg;
    int dmax = max(deg, __shfl_xor_sync(0xffffffffu, deg, 16));

    float4 al = *(const float4*)&attl[c];
    float4 ar = *(const float4*)&attr[c];
    float4 xd = valid ? *(const float4*)&xl[(size_t)node * HC + c]
                      : make_float4(0.f, 0.f, 0.f, 0.f);
    float4 r;
    r.x = ar.x * xd.x; r.y = ar.y * xd.y; r.z = ar.z * xd.z; r.w = ar.w * xd.w;

    float4 a = make_float4(0.f, 0.f, 0.f, 0.f);
    float4 s = make_float4(0.f, 0.f, 0.f, 0.f);

    int last = (end > 0) ? end - 1 : 0;   // safe clamp for predicated-off loads

#define STEP(XS)                                                             \
    {                                                                        \
        float e0 = fmaf(al.x, (XS).x, r.x);                                  \
        float e1 = fmaf(al.y, (XS).y, r.y);                                  \
        float e2 = fmaf(al.z, (XS).z, r.z);                                  \
        float e3 = fmaf(al.w, (XS).w, r.w);                                  \
        e0 = fmaxf(e0, NEGS * e0); e1 = fmaxf(e1, NEGS * e1);                \
        e2 = fmaxf(e2, NEGS * e2); e3 = fmaxf(e3, NEGS * e3);                \
        float p0 = __expf(e0), p1 = __expf(e1);                              \
        float p2 = __expf(e2), p3 = __expf(e3);                              \
        s.x += p0; s.y += p1; s.z += p2; s.w += p3;                          \
        a.x = fmaf((XS).x, p0, a.x); a.y = fmaf((XS).y, p1, a.y);            \
        a.z = fmaf((XS).z, p2, a.z); a.w = fmaf((XS).w, p3, a.w);            \
    }

    for (int j = 0; j < dmax; j += 4) {
        int idx[4];
#pragma unroll
        for (int u = 0; u < 4; u++) {
            int t = beg + j + u;
            idx[u] = __ldg(&adj[t < end ? t : last]);
        }
        float4 xv[4];
#pragma unroll
        for (int u = 0; u < 4; u++)
            xv[u] = __ldg((const float4*)&xl[(size_t)idx[u] * HC + c]);
#pragma unroll
        for (int u = 0; u < 4; u++)
            if (j + u < deg) STEP(xv[u])
    }
#undef STEP

    if (valid) {
        float4 o;
        o.x = fmaxf(__fdividef(a.x, s.x + 1e-16f), 0.f);
        o.y = fmaxf(__fdividef(a.y, s.y + 1e-16f), 0.f);
        o.z = fmaxf(__fdividef(a.z, s.z + 1e-16f), 0.f);
        o.w = fmaxf(__fdividef(a.w, s.w + 1e-16f), 0.f);
        *(float4*)&h[(size_t)node * HC + c] = o;
    }
}

// ------------------------------------- fuse post_mp weights: Wp = Wp2 @ Wp1
__global__ void fuse_kernel(const float* __restrict__ Wp1, const float* __restrict__ bp1,
                            const float* __restrict__ Wp2, const float* __restrict__ bp2,
                            float* __restrict__ Wp, float* __restrict__ bp) {
    int i = blockIdx.x * blockDim.x + threadIdx.x;
    if (i < OUTC * HC) {
        int j = i / HC, k = i % HC;
        float a = 0.f;
#pragma unroll
        for (int t = 0; t < 32; t++) a += Wp2[j * 32 + t] * Wp1[t * HC + k];
        Wp[i] = a;
    }
    if (i < OUTC) {
        float a = bp2[i];
#pragma unroll
        for (int t = 0; t < 32; t++) a += Wp2[i * 32 + t] * bp1[t];
        bp[i] = a;
    }
}

// ------------------------------- epilogue: out = log_softmax(h @ Wp^T + bp)
__global__ __launch_bounds__(256) void post_kernel(const float* __restrict__ h,
                                                   const float* __restrict__ Wp,
                                                   const float* __restrict__ bp,
                                                   float* __restrict__ out, int n) {
    __shared__ float sWp[OUTC * HC];
    __shared__ float sh[4][HC];
    __shared__ float sv[4][OUTC];
    __shared__ float sm[4], sl[4];

    for (int i = threadIdx.x; i < OUTC * HC; i += 256) sWp[i] = Wp[i];

    int g  = threadIdx.x >> 6;
    int lt = threadIdx.x & 63;
    int node = blockIdx.x * 4 + g;
    bool valid = node < n;

    sh[g][lt] = valid ? h[(size_t)node * HC + lt] : 0.f;
    __syncthreads();

    if (lt < OUTC) {
        float a = bp[lt];
#pragma unroll
        for (int k = 0; k < HC; k++) a += sh[g][k] * sWp[lt * HC + k];
        sv[g][lt] = a;
    }
    __syncthreads();

    if (lt == 0) {
        float m = -1e30f;
#pragma unroll
        for (int j = 0; j < OUTC; j++) m = fmaxf(m, sv[g][j]);
        float l = 0.f;
#pragma unroll
        for (int j = 0; j < OUTC; j++) l += __expf(sv[g][j] - m);
        sm[g] = m;
        sl[g] = logf(l);
    }
    __syncthreads();

    if (valid && lt < OUTC)
        out[(size_t)node * OUTC + lt] = sv[g][lt] - sm[g] - sl[g];
}

// ---------------------------------------------------------------------------
extern "C" void kernel_launch(void* const* d_in, const int* in_sizes, int n_in,
                              void* d_out, int out_size) {
    const float* x   = (const float*)d_in[0];
    const int*   ei  = (const int*)  d_in[1];
    const float* W1  = (const float*)d_in[2];
    const float* b1  = (const float*)d_in[3];
    const float* al1 = (const float*)d_in[4];
    const float* ar1 = (const float*)d_in[5];
    const float* W2  = (const float*)d_in[6];
    const float* b2  = (const float*)d_in[7];
    const float* al2 = (const float*)d_in[8];
    const float* ar2 = (const float*)d_in[9];
    const float* Wp1 = (const float*)d_in[10];
    const float* bp1 = (const float*)d_in[11];
    const float* Wp2 = (const float*)d_in[12];
    const float* bp2 = (const float*)d_in[13];
    float* out = (float*)d_out;

    int n  = in_sizes[0] / 128;
    int ne = in_sizes[1] / 2;
    const int* src = ei;
    const int* dst = ei + ne;

    float *xl, *h, *Wp, *bp;
    int *deg, *cur, *off, *adj, *bsum;
    cudaGetSymbolAddress((void**)&xl,   g_xl);
    cudaGetSymbolAddress((void**)&h,    g_h);
    cudaGetSymbolAddress((void**)&deg,  g_deg);
    cudaGetSymbolAddress((void**)&cur,  g_cur);
    cudaGetSymbolAddress((void**)&off,  g_off);
    cudaGetSymbolAddress((void**)&adj,  g_adj);
    cudaGetSymbolAddress((void**)&bsum, g_bsum);
    cudaGetSymbolAddress((void**)&Wp,   g_Wp);
    cudaGetSymbolAddress((void**)&bp,   g_bp);

    dim3 blk(256);
    int gGemm = (n + 63) / 64;
    int gN    = (n + 255) / 256;
    int gE    = (ne + 255) / 256;
    int nb    = (n + 1023) / 1024;
    int gNode = (n * 16 + 255) / 256;     // 2 nodes per warp
    int gPost = (n + 3) / 4;

    // 0: layer-1 GEMM (+ deg zeroing piggybacked)
    gemm64<128><<<gGemm, blk>>>(x, W1, b1, xl, n, deg, n);
    // 1-4: CSR build
    hist_kernel<<<gE, blk>>>(dst, deg, ne);
    scan1_kernel<<<nb, 1024>>>(deg, off, bsum, n);
    scan23_kernel<<<gN, blk>>>(off, bsum, cur, n, nb);
    scatter_kernel<<<gE, blk>>>(src, dst, off, cur, adj, ne);
    // 5: layer-1 edge pass  (profiled slot)
    gat_node_kernel<<<gNode, blk>>>(adj, off, xl, al1, ar1, h, n);
    // 6-7: layer 2
    gemm64<64><<<gGemm, blk>>>(h, W2, b2, xl, n, nullptr, 0);
    gat_node_kernel<<<gNode, blk>>>(adj, off, xl, al2, ar2, h, n);
    // 8-9: fused post-MP + log_softmax
    fuse_kernel<<<10, blk>>>(Wp1, bp1, Wp2, bp2, Wp, bp);
    post_kernel<<<gPost, blk>>>(h, Wp, bp, out, n);
}

// round 8
// speedup vs baseline: 1.0107x; 1.0107x over previous
#include <cuda_runtime.h>
#include <math.h>

#define NN 100000
#define EE 1600000
#define HC 64          // H*C = 2*32
#define OUTC 40
#define NEGS 0.2f
#define NB_SCAN ((NN + 1023) / 1024)

// ---------------- scratch buffers (device globals; zero-init at load) ------
__device__ float g_xl [(size_t)NN * HC];   // transformed features (per layer)
__device__ float g_h  [(size_t)NN * HC];   // layer output (relu'd)
__device__ int   g_deg[NN];                // degree histogram (zeroed by post_kernel)
__device__ int   g_cur[NN];                // scatter cursor (zeroed in scan)
__device__ int   g_off[NN];                // CSR offsets, exclusive WITHIN chunk
__device__ int   g_gpref[NB_SCAN];         // per-chunk exclusive base
__device__ int   g_adj[EE];                // CSR adjacency: src ids grouped by dst
__device__ int   g_ctr[1];                 // scan last-block ticket (self-resetting)
__device__ float g_Wp [OUTC * HC];         // fused Wp2@Wp1  [40,64]
__device__ float g_bp [OUTC];              // fused bias

// ------------------------------------------------------------ GEMM body
// Y[rowBase..rowBase+64, 0..64) = X @ W^T + b  (one 64-row tile per call)
template<int IC>
__device__ __forceinline__ void gemm_body(const float* __restrict__ X,
                                          const float* __restrict__ W,
                                          const float* __restrict__ b,
                                          float* __restrict__ Y, int n,
                                          int rowBase) {
    __shared__ float sX[64][33];
    __shared__ float sW[64][33];
    const int tx = threadIdx.x & 15;
    const int ty = threadIdx.x >> 4;

    float acc[4][4];
#pragma unroll
    for (int i = 0; i < 4; i++)
#pragma unroll
        for (int j = 0; j < 4; j++) acc[i][j] = 0.f;

    for (int k0 = 0; k0 < IC; k0 += 32) {
#pragma unroll
        for (int l = 0; l < 8; l++) {
            int idx = threadIdx.x + l * 256;
            int r = idx >> 5, kk = idx & 31;
            int row = rowBase + r;
            sX[r][kk] = (row < n) ? X[(size_t)row * IC + k0 + kk] : 0.f;
            sW[r][kk] = W[(size_t)r * IC + k0 + kk];
        }
        __syncthreads();
#pragma unroll
        for (int kk = 0; kk < 32; kk++) {
            float xv[4], wv[4];
#pragma unroll
            for (int i = 0; i < 4; i++) xv[i] = sX[ty * 4 + i][kk];
#pragma unroll
            for (int j = 0; j < 4; j++) wv[j] = sW[tx * 4 + j][kk];
#pragma unroll
            for (int i = 0; i < 4; i++)
#pragma unroll
                for (int j = 0; j < 4; j++) acc[i][j] += xv[i] * wv[j];
        }
        __syncthreads();
    }
#pragma unroll
    for (int i = 0; i < 4; i++) {
        int row = rowBase + ty * 4 + i;
        if (row < n) {
#pragma unroll
            for (int j = 0; j < 4; j++) {
                int col = tx * 4 + j;
                Y[(size_t)row * HC + col] = acc[i][j] + b[col];
            }
        }
    }
}

template<int IC>
__global__ __launch_bounds__(256) void gemm64(const float* __restrict__ X,
                                              const float* __restrict__ W,
                                              const float* __restrict__ b,
                                              float* __restrict__ Y, int n) {
    gemm_body<IC>(X, W, b, Y, n, blockIdx.x * 64);
}

// ----------------------------------------------------------- CSR build chain
// launch 0: degree histogram (deg pre-zeroed by previous call's post_kernel)
__global__ void hist_kernel(const int* __restrict__ dst, int* __restrict__ deg, int ne) {
    int e = blockIdx.x * blockDim.x + threadIdx.x;
    if (e < ne) atomicAdd(&deg[dst[e]], 1);
}

// launch 1: single-pass scan. off[i] = exclusive prefix WITHIN 1024-chunk,
// gpref[c] = exclusive chunk base (fixed up by the last block to finish).
__global__ __launch_bounds__(1024) void scan_kernel(const int* __restrict__ deg,
                                                    int* __restrict__ off,
                                                    int* __restrict__ cur,
                                                    int* __restrict__ gpref,
                                                    int* __restrict__ ctr,
                                                    int n, int nb) {
    __shared__ int sm[1024];
    __shared__ int amLast;
    int t = threadIdx.x;
    int i = blockIdx.x * 1024 + t;
    int v = (i < n) ? deg[i] : 0;
    sm[t] = v;
    __syncthreads();
#pragma unroll
    for (int d = 1; d < 1024; d <<= 1) {
        int add = (t >= d) ? sm[t - d] : 0;
        __syncthreads();
        sm[t] += add;
        __syncthreads();
    }
    if (i < n) { off[i] = sm[t] - v; cur[i] = 0; }
    if (t == 1023) gpref[blockIdx.x] = sm[1023];   // chunk total (temp)
    __threadfence();
    __syncthreads();
    if (t == 0) amLast = (atomicAdd(ctr, 1) == gridDim.x - 1);
    __syncthreads();
    if (amLast) {
        int tv = (t < nb) ? gpref[t] : 0;
        sm[t] = tv;
        __syncthreads();
#pragma unroll
        for (int d = 1; d < 1024; d <<= 1) {
            int add = (t >= d) ? sm[t - d] : 0;
            __syncthreads();
            sm[t] += add;
            __syncthreads();
        }
        if (t < nb) gpref[t] = sm[t] - tv;          // exclusive base
        if (t == 0) *ctr = 0;                        // reset for next call
    }
}

// launch 2 (fat): blocks [0,gE) scatter edges; blocks [gE,..) layer-1 GEMM.
__global__ __launch_bounds__(256) void scatter_gemm_kernel(
    const int* __restrict__ src, const int* __restrict__ dst,
    const int* __restrict__ off, const int* __restrict__ gpref,
    int* __restrict__ cur, int* __restrict__ adj, int ne, int gE,
    const float* __restrict__ X, const float* __restrict__ W,
    const float* __restrict__ b, float* __restrict__ Y, int n) {
    if ((int)blockIdx.x < gE) {
        int e = blockIdx.x * 256 + threadIdx.x;
        if (e < ne) {
            int d = dst[e];
            int pos = gpref[d >> 10] + off[d] + atomicAdd(&cur[d], 1);
            adj[pos] = src[e];
        }
    } else {
        gemm_body<128>(X, W, b, Y, n, (blockIdx.x - gE) * 64);
    }
}

// ----------------------------------------- node-centric fused GAT edge pass
// One warp per dst node; lane owns channels [2*lane, 2*lane+1]. (R3 layout)
__global__ __launch_bounds__(256) void gat_node_kernel(
    const int* __restrict__ adj, const int* __restrict__ off,
    const int* __restrict__ gpref, const int* __restrict__ deg,
    const float* __restrict__ xl,
    const float* __restrict__ attl, const float* __restrict__ attr,
    float* __restrict__ h, int n) {
    int node = (blockIdx.x * 256 + threadIdx.x) >> 5;
    int lane = threadIdx.x & 31;
    if (node >= n) return;
    int c = lane * 2;

    int beg = __ldg(&gpref[node >> 10]) + __ldg(&off[node]);
    int end = beg + __ldg(&deg[node]);

    float2 al = *(const float2*)&attl[c];
    float2 ar = *(const float2*)&attr[c];
    float2 xd = *(const float2*)&xl[(size_t)node * HC + c];
    float rx = ar.x * xd.x, ry = ar.y * xd.y;

    float a0 = 0.f, a1 = 0.f, s0 = 0.f, s1 = 0.f;
    int j = beg;

#define STEP(XS)                                                             \
    {                                                                        \
        float e0 = fmaf(al.x, (XS).x, rx);                                   \
        float e1 = fmaf(al.y, (XS).y, ry);                                   \
        e0 = fmaxf(e0, NEGS * e0);                                           \
        e1 = fmaxf(e1, NEGS * e1);                                           \
        float p0 = __expf(e0), p1 = __expf(e1);                              \
        s0 += p0; s1 += p1;                                                  \
        a0 = fmaf((XS).x, p0, a0); a1 = fmaf((XS).y, p1, a1);                \
    }

    // 8-wide body: all index loads, then all gathers, then math (MLP=8)
    for (; j + 8 <= end; j += 8) {
        int idx[8];
#pragma unroll
        for (int u = 0; u < 8; u++) idx[u] = __ldg(&adj[j + u]);
        float2 xv[8];
#pragma unroll
        for (int u = 0; u < 8; u++)
            xv[u] = __ldg((const float2*)&xl[(size_t)idx[u] * HC + c]);
#pragma unroll
        for (int u = 0; u < 8; u++) STEP(xv[u])
    }
    for (; j < end; j++) {
        int i0 = __ldg(&adj[j]);
        float2 x0 = __ldg((const float2*)&xl[(size_t)i0 * HC + c]);
        STEP(x0)
    }
#undef STEP

    float2 o;
    o.x = fmaxf(__fdividef(a0, s0 + 1e-16f), 0.f);
    o.y = fmaxf(__fdividef(a1, s1 + 1e-16f), 0.f);
    *(float2*)&h[(size_t)node * HC + c] = o;
}

// ------------------------------------- fuse post_mp weights: Wp = Wp2 @ Wp1
__global__ void fuse_kernel(const float* __restrict__ Wp1, const float* __restrict__ bp1,
                            const float* __restrict__ Wp2, const float* __restrict__ bp2,
                            float* __restrict__ Wp, float* __restrict__ bp) {
    int i = blockIdx.x * blockDim.x + threadIdx.x;
    if (i < OUTC * HC) {
        int j = i / HC, k = i % HC;
        float a = 0.f;
#pragma unroll
        for (int t = 0; t < 32; t++) a += Wp2[j * 32 + t] * Wp1[t * HC + k];
        Wp[i] = a;
    }
    if (i < OUTC) {
        float a = bp2[i];
#pragma unroll
        for (int t = 0; t < 32; t++) a += Wp2[i * 32 + t] * bp1[t];
        bp[i] = a;
    }
}

// ---------------- epilogue: out = log_softmax(h @ Wp^T + bp); zero deg -----
__global__ __launch_bounds__(256) void post_kernel(const float* __restrict__ h,
                                                   const float* __restrict__ Wp,
                                                   const float* __restrict__ bp,
                                                   float* __restrict__ out,
                                                   int* __restrict__ degz, int n) {
    int gid = blockIdx.x * 256 + threadIdx.x;
    if (gid < n) degz[gid] = 0;      // prepare hist for NEXT call

    __shared__ float sWp[OUTC * HC];
    __shared__ float sh[4][HC];
    __shared__ float sv[4][OUTC];
    __shared__ float sm[4], sl[4];

    for (int i = threadIdx.x; i < OUTC * HC; i += 256) sWp[i] = Wp[i];

    int g  = threadIdx.x >> 6;
    int lt = threadIdx.x & 63;
    int node = blockIdx.x * 4 + g;
    bool valid = node < n;

    sh[g][lt] = valid ? h[(size_t)node * HC + lt] : 0.f;
    __syncthreads();

    if (lt < OUTC) {
        float a = bp[lt];
#pragma unroll
        for (int k = 0; k < HC; k++) a += sh[g][k] * sWp[lt * HC + k];
        sv[g][lt] = a;
    }
    __syncthreads();

    if (lt == 0) {
        float m = -1e30f;
#pragma unroll
        for (int j = 0; j < OUTC; j++) m = fmaxf(m, sv[g][j]);
        float l = 0.f;
#pragma unroll
        for (int j = 0; j < OUTC; j++) l += __expf(sv[g][j] - m);
        sm[g] = m;
        sl[g] = logf(l);
    }
    __syncthreads();

    if (valid && lt < OUTC)
        out[(size_t)node * OUTC + lt] = sv[g][lt] - sm[g] - sl[g];
}

// ---------------------------------------------------------------------------
extern "C" void kernel_launch(void* const* d_in, const int* in_sizes, int n_in,
                              void* d_out, int out_size) {
    const float* x   = (const float*)d_in[0];
    const int*   ei  = (const int*)  d_in[1];
    const float* W1  = (const float*)d_in[2];
    const float* b1  = (const float*)d_in[3];
    const float* al1 = (const float*)d_in[4];
    const float* ar1 = (const float*)d_in[5];
    const float* W2  = (const float*)d_in[6];
    const float* b2  = (const float*)d_in[7];
    const float* al2 = (const float*)d_in[8];
    const float* ar2 = (const float*)d_in[9];
    const float* Wp1 = (const float*)d_in[10];
    const float* bp1 = (const float*)d_in[11];
    const float* Wp2 = (const float*)d_in[12];
    const float* bp2 = (const float*)d_in[13];
    float* out = (float*)d_out;

    int n  = in_sizes[0] / 128;
    int ne = in_sizes[1] / 2;
    const int* src = ei;
    const int* dst = ei + ne;

    float *xl, *h, *Wp, *bp;
    int *deg, *cur, *off, *adj, *gpref, *ctr;
    cudaGetSymbolAddress((void**)&xl,    g_xl);
    cudaGetSymbolAddress((void**)&h,     g_h);
    cudaGetSymbolAddress((void**)&deg,   g_deg);
    cudaGetSymbolAddress((void**)&cur,   g_cur);
    cudaGetSymbolAddress((void**)&off,   g_off);
    cudaGetSymbolAddress((void**)&adj,   g_adj);
    cudaGetSymbolAddress((void**)&gpref, g_gpref);
    cudaGetSymbolAddress((void**)&ctr,   g_ctr);
    cudaGetSymbolAddress((void**)&Wp,    g_Wp);
    cudaGetSymbolAddress((void**)&bp,    g_bp);

    dim3 blk(256);
    int gGemm = (n + 63) / 64;
    int gE    = (ne + 255) / 256;
    int nb    = (n + 1023) / 1024;
    int gNode = (n * 32 + 255) / 256;     // 1 node per warp
    int gPost = (n + 3) / 4;

    // 0: degree histogram (deg zeroed by previous call's post_kernel / load init)
    hist_kernel<<<gE, blk>>>(dst, deg, ne);
    // 1: single-pass scan (chunk-relative offsets + chunk bases)
    scan_kernel<<<nb, 1024>>>(deg, off, cur, gpref, ctr, n, nb);
    // 2: scatter + layer-1 GEMM fused (independent block ranges)
    scatter_gemm_kernel<<<gE + gGemm, blk>>>(src, dst, off, gpref, cur, adj, ne, gE,
                                             x, W1, b1, xl, n);
    // 3: layer-1 edge pass  (PROFILED SLOT)
    gat_node_kernel<<<gNode, blk>>>(adj, off, gpref, deg, xl, al1, ar1, h, n);
    // 4-5: layer 2
    gemm64<64><<<gGemm, blk>>>(h, W2, b2, xl, n);
    gat_node_kernel<<<gNode, blk>>>(adj, off, gpref, deg, xl, al2, ar2, h, n);
    // 6-7: fused post-MP + log_softmax (+ deg re-zero for next call)
    fuse_kernel<<<10, blk>>>(Wp1, bp1, Wp2, bp2, Wp, bp);
    post_kernel<<<gPost, blk>>>(h, Wp, bp, out, deg, n);
}